// round 4
// baseline (speedup 1.0000x reference)
#include <cuda_runtime.h>
#include <cstdint>
#include <cstddef>

#define B_ 2
#define S_ 2048
#define D_ 64
#define H_ 8

#define TM 128   // rows per CTA
#define TN 64    // t-columns per main-loop iteration
#define NTHREADS 128

// pitch in 32-bit words; 72 ≡ 8 (mod 32): conflict-free LDS.64 fragment loads,
// conflict-free STS.128 staging, conflict-free bias LDS.64.
#define PITCH 72

#define SMEM_WORDS ((TM + TN + TN + TM) * PITCH)   // sQ, sK, sV, sPB
#define SMEM_BYTES (SMEM_WORDS * 4)                // 110,592 B -> 2 CTAs/SM

__device__ __forceinline__ uint32_t f2tf(float x) {
    uint32_t r;
    asm("cvt.rna.tf32.f32 %0, %1;" : "=r"(r) : "f"(x));
    return r;
}

__device__ __forceinline__ void mma_tf32(float c[4],
                                         uint32_t a0, uint32_t a1, uint32_t a2, uint32_t a3,
                                         uint32_t b0, uint32_t b1) {
    asm volatile(
        "mma.sync.aligned.m16n8k8.row.col.f32.tf32.tf32.f32 "
        "{%0,%1,%2,%3}, {%4,%5,%6,%7}, {%8,%9}, {%0,%1,%2,%3};\n"
        : "+f"(c[0]), "+f"(c[1]), "+f"(c[2]), "+f"(c[3])
        : "r"(a0), "r"(a1), "r"(a2), "r"(a3), "r"(b0), "r"(b1));
}

__device__ __forceinline__ void cp_async16(uint32_t dst_smem, const void* src) {
    asm volatile("cp.async.cg.shared.global [%0], [%1], 16;\n"
                 :: "r"(dst_smem), "l"(src));
}

// Pair-permuted staging: within each 8-col block, logical col w -> physical
// word perm(w) = (w&3)*2 + (w>>2), so mma fragment pairs (w, w+4) are adjacent
// -> LDS.64 operand loads. Thread pair (lane ^ 1) covers one 8-col block via
// shuffles; each thread emits one STS.128.
__device__ __forceinline__ void store_permuted(uint32_t* base, int row, int c4,
                                               float4 v, float scale) {
    float s0 = __shfl_xor_sync(0xffffffffu, v.x, 1);
    float s1 = __shfl_xor_sync(0xffffffffu, v.y, 1);
    float s2 = __shfl_xor_sync(0xffffffffu, v.z, 1);
    float s3 = __shfl_xor_sync(0xffffffffu, v.w, 1);
    int blk  = c4 >> 1;
    int half = c4 & 1;
    uint4 o;
    if (half == 0) {
        o.x = f2tf(v.x * scale); o.y = f2tf(s0 * scale);
        o.z = f2tf(v.y * scale); o.w = f2tf(s1 * scale);
    } else {
        o.x = f2tf(s2 * scale);  o.y = f2tf(v.z * scale);
        o.z = f2tf(s3 * scale);  o.w = f2tf(v.w * scale);
    }
    *reinterpret_cast<uint4*>(base + row * PITCH + blk * 8 + half * 4) = o;
}

__global__ void __launch_bounds__(NTHREADS, 2)
attn_bias_kernel(const float* __restrict__ x1,
                 const float* __restrict__ x2,
                 const float* __restrict__ x3,
                 const float* __restrict__ x4,
                 float* __restrict__ out) {
    const int mt = blockIdx.x;   // 0..15
    const int h  = blockIdx.y;   // 0..7
    const int b  = blockIdx.z;   // 0..1

    const int tid  = threadIdx.x;
    const int warp = tid >> 5;
    const int lane = tid & 31;
    const int r = lane >> 2;
    const int q = lane & 3;

    extern __shared__ uint32_t smem[];
    uint32_t* sQ  = smem;                 // [TM][PITCH] permuted tf32 (pre-scaled)
    uint32_t* sK  = sQ + TM * PITCH;      // [TN][PITCH] permuted tf32
    uint32_t* sV  = sK + TN * PITCH;      // [TN][PITCH] plain    tf32
    uint32_t* sPB = sV + TN * PITCH;      // [TM][PITCH] bias (linear fp32) then P (permuted tf32)
    const float* sPBf = reinterpret_cast<const float*>(sPB);
    uint32_t sPB_addr = (uint32_t)__cvta_generic_to_shared(sPB);

    // ---- stage Q tile once (pre-scaled by 1/sqrt(D) = 0.125) ----
    const float* qbase = x1 + ((size_t)b * S_ + (size_t)mt * TM) * D_;
    #pragma unroll
    for (int j = 0; j < 16; ++j) {
        int i = j * NTHREADS + tid;
        int row = i >> 4;
        int c4  = i & 15;
        float4 v = *reinterpret_cast<const float4*>(qbase + row * D_ + c4 * 4);
        store_permuted(sQ, row, c4, v, 0.125f);
    }

    float accO[2][8][4];
    #pragma unroll
    for (int mf = 0; mf < 2; ++mf)
        #pragma unroll
        for (int n = 0; n < 8; ++n)
            #pragma unroll
            for (int j = 0; j < 4; ++j) accO[mf][n][j] = 0.0f;
    float lsum[2][2] = {{0.0f, 0.0f}, {0.0f, 0.0f}};

    const float* kbase = x2 + (size_t)b * S_ * D_;
    const float* vbase = x4 + (size_t)b * S_ * D_;
    const float* biasbase = x3 + (((size_t)b * H_ + h) * S_ + (size_t)mt * TM) * S_;

    const int R0 = warp * 32;
    const int R1 = warp * 32 + 16;
    const int pp0 = (q & 1) * 4 + (q >> 1);   // perm(2q)
    const int pp1 = pp0 + 2;                  // perm(2q+1)

    for (int t0 = 0; t0 < S_; t0 += TN) {
        __syncthreads();   // prev iteration's sK/sV/sPB readers done

        // ---- issue bias tile cp.async (TM x TN floats, linear, pitch 72) ----
        const float* btile = biasbase + t0;
        #pragma unroll
        for (int j = 0; j < 16; ++j) {
            int i = j * NTHREADS + tid;
            int row = i >> 4;
            int c4  = i & 15;
            cp_async16(sPB_addr + (uint32_t)(row * PITCH + c4 * 4) * 4,
                       btile + (size_t)row * S_ + c4 * 4);
        }
        asm volatile("cp.async.commit_group;\n" ::: "memory");

        // ---- stage K (permuted) and V (plain) tiles ----
        #pragma unroll
        for (int j = 0; j < 8; ++j) {
            int i = j * NTHREADS + tid;
            int row = i >> 4;
            int c4  = i & 15;
            float4 kv = *reinterpret_cast<const float4*>(kbase + (size_t)(t0 + row) * D_ + c4 * 4);
            store_permuted(sK, row, c4, kv, 1.0f);
            float4 vv = *reinterpret_cast<const float4*>(vbase + (size_t)(t0 + row) * D_ + c4 * 4);
            uint4 o;
            o.x = f2tf(vv.x); o.y = f2tf(vv.y); o.z = f2tf(vv.z); o.w = f2tf(vv.w);
            *reinterpret_cast<uint4*>(sV + row * PITCH + c4 * 4) = o;
        }
        __syncthreads();   // sK/sV ready (bias may still be in flight)

        // ---- S = Q @ K^T  (per warp: 32 rows x 64 cols), bias lands under MMA ----
        float c[2][8][4];
        #pragma unroll
        for (int mf = 0; mf < 2; ++mf)
            #pragma unroll
            for (int n = 0; n < 8; ++n)
                #pragma unroll
                for (int j = 0; j < 4; ++j) c[mf][n][j] = 0.0f;

        #pragma unroll
        for (int k = 0; k < 8; ++k) {
            uint2 qa0 = *reinterpret_cast<const uint2*>(sQ + (R0 + r)     * PITCH + 8 * k + 2 * q);
            uint2 qb0 = *reinterpret_cast<const uint2*>(sQ + (R0 + r + 8) * PITCH + 8 * k + 2 * q);
            uint2 qa1 = *reinterpret_cast<const uint2*>(sQ + (R1 + r)     * PITCH + 8 * k + 2 * q);
            uint2 qb1 = *reinterpret_cast<const uint2*>(sQ + (R1 + r + 8) * PITCH + 8 * k + 2 * q);
            #pragma unroll
            for (int n = 0; n < 8; ++n) {
                uint2 kb = *reinterpret_cast<const uint2*>(sK + (8 * n + r) * PITCH + 8 * k + 2 * q);
                mma_tf32(c[0][n], qa0.x, qb0.x, qa0.y, qb0.y, kb.x, kb.y);
                mma_tf32(c[1][n], qa1.x, qb1.x, qa1.y, qb1.y, kb.x, kb.y);
            }
        }

        // ---- bias is needed now; wait + CTA barrier (copiers != readers) ----
        asm volatile("cp.async.wait_group 0;\n" ::: "memory");
        __syncthreads();

        // ---- logits + bias -> exp -> P (overwrite sPB, permuted tf32) ----
        #pragma unroll
        for (int mf = 0; mf < 2; ++mf) {
            const int R = (mf == 0) ? R0 : R1;
            float2 bb0[8], bb1[8];
            #pragma unroll
            for (int n = 0; n < 8; ++n) {
                bb0[n] = *reinterpret_cast<const float2*>(sPBf + (size_t)(R + r) * PITCH + 8 * n + 2 * q);
                bb1[n] = *reinterpret_cast<const float2*>(sPBf + (size_t)(R + r + 8) * PITCH + 8 * n + 2 * q);
            }
            __syncwarp();   // all bias reads for these 16 rows done before any P write
            #pragma unroll
            for (int n = 0; n < 8; ++n) {
                float p0 = __expf(c[mf][n][0] + bb0[n].x);
                float p1 = __expf(c[mf][n][1] + bb0[n].y);
                float p2 = __expf(c[mf][n][2] + bb1[n].x);
                float p3 = __expf(c[mf][n][3] + bb1[n].y);
                lsum[mf][0] += p0 + p1;
                lsum[mf][1] += p2 + p3;
                sPB[(R + r) * PITCH + 8 * n + pp0]     = f2tf(p0);
                sPB[(R + r) * PITCH + 8 * n + pp1]     = f2tf(p1);
                sPB[(R + r + 8) * PITCH + 8 * n + pp0] = f2tf(p2);
                sPB[(R + r + 8) * PITCH + 8 * n + pp1] = f2tf(p3);
            }
        }
        __syncwarp();   // each warp reads only its own 32 rows of P

        // ---- O += P @ V ----
        #pragma unroll
        for (int k = 0; k < 8; ++k) {
            uint2 pa0 = *reinterpret_cast<const uint2*>(sPB + (R0 + r)     * PITCH + 8 * k + 2 * q);
            uint2 pb0 = *reinterpret_cast<const uint2*>(sPB + (R0 + r + 8) * PITCH + 8 * k + 2 * q);
            uint2 pa1 = *reinterpret_cast<const uint2*>(sPB + (R1 + r)     * PITCH + 8 * k + 2 * q);
            uint2 pb1 = *reinterpret_cast<const uint2*>(sPB + (R1 + r + 8) * PITCH + 8 * k + 2 * q);
            #pragma unroll
            for (int n = 0; n < 8; ++n) {
                uint32_t b0 = sV[(8 * k + q)     * PITCH + 8 * n + r];
                uint32_t b1 = sV[(8 * k + q + 4) * PITCH + 8 * n + r];
                mma_tf32(accO[0][n], pa0.x, pb0.x, pa0.y, pb0.y, b0, b1);
                mma_tf32(accO[1][n], pa1.x, pb1.x, pa1.y, pb1.y, b0, b1);
            }
        }
    }

    // ---- finalize ----
    #pragma unroll
    for (int mf = 0; mf < 2; ++mf)
        #pragma unroll
        for (int j = 0; j < 2; ++j) {
            lsum[mf][j] += __shfl_xor_sync(0xffffffffu, lsum[mf][j], 1);
            lsum[mf][j] += __shfl_xor_sync(0xffffffffu, lsum[mf][j], 2);
        }

    float inv[2][2];
    inv[0][0] = 1.0f / lsum[0][0]; inv[0][1] = 1.0f / lsum[0][1];
    inv[1][0] = 1.0f / lsum[1][0]; inv[1][1] = 1.0f / lsum[1][1];

    float* obase = out + (((size_t)b * H_ + h) * S_ + (size_t)mt * TM) * D_;
    #pragma unroll
    for (int mf = 0; mf < 2; ++mf) {
        const int R = (mf == 0) ? R0 : R1;
        #pragma unroll
        for (int n = 0; n < 8; ++n) {
            float2 v0 = make_float2(accO[mf][n][0] * inv[mf][0], accO[mf][n][1] * inv[mf][0]);
            float2 v1 = make_float2(accO[mf][n][2] * inv[mf][1], accO[mf][n][3] * inv[mf][1]);
            *reinterpret_cast<float2*>(obase + (size_t)(R + r) * D_ + 8 * n + 2 * q) = v0;
            *reinterpret_cast<float2*>(obase + (size_t)(R + r + 8) * D_ + 8 * n + 2 * q) = v1;
        }
    }
}

extern "C" void kernel_launch(void* const* d_in, const int* in_sizes, int n_in,
                              void* d_out, int out_size) {
    (void)in_sizes; (void)n_in; (void)out_size;
    const float* x1 = (const float*)d_in[0];
    const float* x2 = (const float*)d_in[1];
    const float* x3 = (const float*)d_in[2];
    const float* x4 = (const float*)d_in[3];
    float* out = (float*)d_out;

    cudaFuncSetAttribute(attn_bias_kernel,
                         cudaFuncAttributeMaxDynamicSharedMemorySize, SMEM_BYTES);

    dim3 grid(S_ / TM, H_, B_);   // 16 x 8 x 2 = 256 CTAs
    attn_bias_kernel<<<grid, NTHREADS, SMEM_BYTES>>>(x1, x2, x3, x4, out);
}

// round 5
// speedup vs baseline: 1.5271x; 1.5271x over previous
#include <cuda_runtime.h>
#include <cstdint>
#include <cstddef>

#define B_ 2
#define S_ 2048
#define D_ 64
#define H_ 8

#define TM 128   // rows per CTA
#define TN 64    // t-columns per main-loop iteration
#define NTHREADS 128

#define PQ 68
#define PK 68
#define PV 72
#define PP 68

#define SMEM_WORDS (TM*PQ + TN*PK + TN*PV + TM*PP)
#define SMEM_BYTES (SMEM_WORDS * 4)

__device__ __forceinline__ uint32_t f2tf(float x) {
    uint32_t r;
    asm("cvt.rna.tf32.f32 %0, %1;" : "=r"(r) : "f"(x));
    return r;
}

__device__ __forceinline__ void mma_tf32(float c[4],
                                         uint32_t a0, uint32_t a1, uint32_t a2, uint32_t a3,
                                         uint32_t b0, uint32_t b1) {
    asm volatile(
        "mma.sync.aligned.m16n8k8.row.col.f32.tf32.tf32.f32 "
        "{%0,%1,%2,%3}, {%4,%5,%6,%7}, {%8,%9}, {%0,%1,%2,%3};\n"
        : "+f"(c[0]), "+f"(c[1]), "+f"(c[2]), "+f"(c[3])
        : "r"(a0), "r"(a1), "r"(a2), "r"(a3), "r"(b0), "r"(b1));
}

__device__ __forceinline__ void cp_async16(uint32_t dst_smem, const float* src) {
    asm volatile("cp.async.cg.shared.global [%0], [%1], 16;\n"
                 :: "r"(dst_smem), "l"(src));
}

__global__ void __launch_bounds__(NTHREADS, 2)
attn_bias_kernel(const float* __restrict__ x1,
                 const float* __restrict__ x2,
                 const float* __restrict__ x3,
                 const float* __restrict__ x4,
                 float* __restrict__ out) {
    const int mt = blockIdx.x;   // 0..15
    const int h  = blockIdx.y;   // 0..7
    const int b  = blockIdx.z;   // 0..1

    const int tid  = threadIdx.x;
    const int warp = tid >> 5;
    const int lane = tid & 31;
    const int r = lane >> 2;     // 0..7
    const int q = lane & 3;      // 0..3

    extern __shared__ uint32_t smem[];
    uint32_t* sQ  = smem;               // [TM][PQ]  tf32 (pre-scaled by 0.125)
    uint32_t* sK  = sQ + TM * PQ;       // [TN][PK]  tf32
    uint32_t* sV  = sK + TN * PK;       // [TN][PV]  tf32
    uint32_t* sPB = sV + TN * PV;       // [TM][PP]  bias fp32, then P tf32 (same slots)
    const float* sPBf = reinterpret_cast<const float*>(sPB);

    // ---- load Q tile (TM x 64) once, pre-scaled (exact: x0.125 = exp shift) ----
    const float* qbase = x1 + ((size_t)b * S_ + (size_t)mt * TM) * D_;
    #pragma unroll
    for (int j = 0; j < 16; ++j) {
        int i = j * NTHREADS + tid;
        int row = i >> 4;
        int c4  = i & 15;
        float4 v = *reinterpret_cast<const float4*>(qbase + row * D_ + c4 * 4);
        uint32_t* dst = sQ + row * PQ + c4 * 4;
        dst[0] = f2tf(v.x * 0.125f); dst[1] = f2tf(v.y * 0.125f);
        dst[2] = f2tf(v.z * 0.125f); dst[3] = f2tf(v.w * 0.125f);
    }

    float accO[2][8][4];
    #pragma unroll
    for (int mf = 0; mf < 2; ++mf)
        #pragma unroll
        for (int n = 0; n < 8; ++n)
            #pragma unroll
            for (int j = 0; j < 4; ++j) accO[mf][n][j] = 0.0f;
    float lsum[2][2] = {{0.0f, 0.0f}, {0.0f, 0.0f}};

    const int R0 = warp * 32;
    const int R1 = warp * 32 + 16;

    // ---- strength-reduced pointers (advance per iteration, no in-loop IMAD) ----
    // K/V staging: thread covers (row = 8j + (tid>>4), c4 = tid&15), j = 0..7
    const int srow = tid >> 4;          // 0..7
    const int sc4  = tid & 15;          // 0..15
    const float* kptr = x2 + (size_t)b * S_ * D_ + (size_t)srow * D_ + sc4 * 4;
    const float* vptr = x4 + (size_t)b * S_ * D_ + (size_t)srow * D_ + sc4 * 4;
    // bias staging is WARP-LOCAL: warp w copies rows 32w..32w+31 (its own rows).
    // lane covers (row = 32w + 2j + (lane>>4), chunk = lane&15), j = 0..15
    const int brow0 = warp * 32 + (lane >> 4);   // row parity base
    const int bc4   = lane & 15;
    const float* bptr = x3 + (((size_t)b * H_ + h) * S_ + (size_t)mt * TM + brow0) * S_
                        + bc4 * 4;
    // smem destinations (byte addresses), loop-invariant bases
    const uint32_t sPB_b = (uint32_t)__cvta_generic_to_shared(sPB)
                         + (uint32_t)(brow0 * PP + bc4 * 4) * 4;
    uint32_t* sKd = sK + srow * PK + sc4 * 4;
    uint32_t* sVd = sV + srow * PV + sc4 * 4;

    for (int t0 = 0; t0 < S_; t0 += TN) {
        __syncthreads();   // prev iteration's sK/sV/sPB readers done

        // ---- issue bias tile cp.async first (overlaps staging + QK MMA) ----
        #pragma unroll
        for (int j = 0; j < 16; ++j) {
            cp_async16(sPB_b + (uint32_t)(2 * j * PP) * 4,        // rows brow0 + 2j
                       bptr + (size_t)(2 * j) * S_);
        }
        asm volatile("cp.async.commit_group;\n" ::: "memory");
        bptr += TN;

        // ---- stage K,V tiles (TN x 64 each), RNA tf32 ----
        #pragma unroll
        for (int j = 0; j < 8; ++j) {
            float4 kv = *reinterpret_cast<const float4*>(kptr + (size_t)(8 * j) * D_);
            uint4 ok;
            ok.x = f2tf(kv.x); ok.y = f2tf(kv.y); ok.z = f2tf(kv.z); ok.w = f2tf(kv.w);
            *reinterpret_cast<uint4*>(sKd + 8 * j * PK) = ok;
            float4 vv = *reinterpret_cast<const float4*>(vptr + (size_t)(8 * j) * D_);
            uint4 ov;
            ov.x = f2tf(vv.x); ov.y = f2tf(vv.y); ov.z = f2tf(vv.z); ov.w = f2tf(vv.w);
            *reinterpret_cast<uint4*>(sVd + 8 * j * PV) = ov;
        }
        kptr += TN * D_;
        vptr += TN * D_;
        __syncthreads();   // sK/sV ready (bias still in flight)

        // ---- S = Q @ K^T  (per warp: 32 rows x 64 cols) ----
        float c[2][8][4];
        #pragma unroll
        for (int mf = 0; mf < 2; ++mf)
            #pragma unroll
            for (int n = 0; n < 8; ++n)
                #pragma unroll
                for (int j = 0; j < 4; ++j) c[mf][n][j] = 0.0f;

        #pragma unroll
        for (int k = 0; k < 8; ++k) {
            uint32_t a0[4], a1[4];
            a0[0] = sQ[(R0 + r) * PQ + 8 * k + q];
            a0[1] = sQ[(R0 + r + 8) * PQ + 8 * k + q];
            a0[2] = sQ[(R0 + r) * PQ + 8 * k + q + 4];
            a0[3] = sQ[(R0 + r + 8) * PQ + 8 * k + q + 4];
            a1[0] = sQ[(R1 + r) * PQ + 8 * k + q];
            a1[1] = sQ[(R1 + r + 8) * PQ + 8 * k + q];
            a1[2] = sQ[(R1 + r) * PQ + 8 * k + q + 4];
            a1[3] = sQ[(R1 + r + 8) * PQ + 8 * k + q + 4];
            #pragma unroll
            for (int n = 0; n < 8; ++n) {
                uint32_t b0 = sK[(8 * n + r) * PK + 8 * k + q];
                uint32_t b1 = sK[(8 * n + r) * PK + 8 * k + q + 4];
                mma_tf32(c[0][n], a0[0], a0[1], a0[2], a0[3], b0, b1);
                mma_tf32(c[1][n], a1[0], a1[1], a1[2], a1[3], b0, b1);
            }
        }

        // ---- bias needed now; warp-local staging -> warp-local wait ----
        asm volatile("cp.async.wait_group 0;\n" ::: "memory");
        __syncwarp();

        // ---- logits + bias -> exp -> P (overwrite same smem slots) ----
        #pragma unroll
        for (int mf = 0; mf < 2; ++mf) {
            const int R = (mf == 0) ? R0 : R1;
            #pragma unroll
            for (int n = 0; n < 8; ++n) {
                float2 bb0 = *reinterpret_cast<const float2*>(sPBf + (R + r) * PP + 8 * n + 2 * q);
                float2 bb1 = *reinterpret_cast<const float2*>(sPBf + (R + r + 8) * PP + 8 * n + 2 * q);
                float p0 = __expf(c[mf][n][0] + bb0.x);
                float p1 = __expf(c[mf][n][1] + bb0.y);
                float p2 = __expf(c[mf][n][2] + bb1.x);
                float p3 = __expf(c[mf][n][3] + bb1.y);
                lsum[mf][0] += p0 + p1;
                lsum[mf][1] += p2 + p3;
                // thread-local RAW: this thread read these exact words above
                uint2 w0; w0.x = f2tf(p0); w0.y = f2tf(p1);
                uint2 w1; w1.x = f2tf(p2); w1.y = f2tf(p3);
                *reinterpret_cast<uint2*>(sPB + (R + r) * PP + 8 * n + 2 * q) = w0;
                *reinterpret_cast<uint2*>(sPB + (R + r + 8) * PP + 8 * n + 2 * q) = w1;
            }
        }
        __syncwarp();   // each warp reads only its own 32 rows of P (cross-lane)

        // ---- O += P @ V ----
        #pragma unroll
        for (int k = 0; k < 8; ++k) {
            uint32_t a0[4], a1[4];
            a0[0] = sPB[(R0 + r) * PP + 8 * k + q];
            a0[1] = sPB[(R0 + r + 8) * PP + 8 * k + q];
            a0[2] = sPB[(R0 + r) * PP + 8 * k + q + 4];
            a0[3] = sPB[(R0 + r + 8) * PP + 8 * k + q + 4];
            a1[0] = sPB[(R1 + r) * PP + 8 * k + q];
            a1[1] = sPB[(R1 + r + 8) * PP + 8 * k + q];
            a1[2] = sPB[(R1 + r) * PP + 8 * k + q + 4];
            a1[3] = sPB[(R1 + r + 8) * PP + 8 * k + q + 4];
            #pragma unroll
            for (int n = 0; n < 8; ++n) {
                uint32_t b0 = sV[(8 * k + q) * PV + 8 * n + r];
                uint32_t b1 = sV[(8 * k + q + 4) * PV + 8 * n + r];
                mma_tf32(accO[0][n], a0[0], a0[1], a0[2], a0[3], b0, b1);
                mma_tf32(accO[1][n], a1[0], a1[1], a1[2], a1[3], b0, b1);
            }
        }
    }

    // ---- finalize: reduce row sums across the quad, divide, store ----
    #pragma unroll
    for (int mf = 0; mf < 2; ++mf)
        #pragma unroll
        for (int j = 0; j < 2; ++j) {
            lsum[mf][j] += __shfl_xor_sync(0xffffffffu, lsum[mf][j], 1);
            lsum[mf][j] += __shfl_xor_sync(0xffffffffu, lsum[mf][j], 2);
        }

    float inv[2][2];
    inv[0][0] = 1.0f / lsum[0][0]; inv[0][1] = 1.0f / lsum[0][1];
    inv[1][0] = 1.0f / lsum[1][0]; inv[1][1] = 1.0f / lsum[1][1];

    float* obase = out + (((size_t)b * H_ + h) * S_ + (size_t)mt * TM) * D_;
    #pragma unroll
    for (int mf = 0; mf < 2; ++mf) {
        const int R = (mf == 0) ? R0 : R1;
        #pragma unroll
        for (int n = 0; n < 8; ++n) {
            float2 v0 = make_float2(accO[mf][n][0] * inv[mf][0], accO[mf][n][1] * inv[mf][0]);
            float2 v1 = make_float2(accO[mf][n][2] * inv[mf][1], accO[mf][n][3] * inv[mf][1]);
            *reinterpret_cast<float2*>(obase + (size_t)(R + r) * D_ + 8 * n + 2 * q) = v0;
            *reinterpret_cast<float2*>(obase + (size_t)(R + r + 8) * D_ + 8 * n + 2 * q) = v1;
        }
    }
}

extern "C" void kernel_launch(void* const* d_in, const int* in_sizes, int n_in,
                              void* d_out, int out_size) {
    (void)in_sizes; (void)n_in; (void)out_size;
    const float* x1 = (const float*)d_in[0];
    const float* x2 = (const float*)d_in[1];
    const float* x3 = (const float*)d_in[2];
    const float* x4 = (const float*)d_in[3];
    float* out = (float*)d_out;

    cudaFuncSetAttribute(attn_bias_kernel,
                         cudaFuncAttributeMaxDynamicSharedMemorySize, SMEM_BYTES);

    dim3 grid(S_ / TM, H_, B_);   // 16 x 8 x 2 = 256 CTAs
    attn_bias_kernel<<<grid, NTHREADS, SMEM_BYTES>>>(x1, x2, x3, x4, out);
}